// round 8
// baseline (speedup 1.0000x reference)
#include <cuda_runtime.h>

// out = chem @ (Wout @ Wv)^T + (Wout @ bv + bout)   (softmax over singleton == 1)
//
// Octet scheme with input-sharing + output-halving:
//   lane o = t&7 loads float2 slot o of a row (coalesced 8B).
//   pair (o, o^1) exchanges float2s (2 SHFL) -> each lane holds input quarter
//   g = o>>1 (4 inputs). Lane computes partials for output HALF H = o&1 only:
//   M footprint = 4 in x 8 out = 16 f32x2 regs (32 regs, half of R7).
//   Reduce-scatter over xor{2,4} (3 ull-shfl + 3 add2) leaves lane with output
//   pair 4H+g, stored at the permuted slot of the same row (still coalesced).
// 32 regs freed -> 3 CTAs/SM (24 warps) under __launch_bounds__(256,3).
// Persistent grid + ping-pong register double-buffering as in R7.
// Weight folding (M = Wout*Wv, c = Wout*bv + bout) is done PER-CTA into smem,
// eliminating the separate setup kernel launch.

#define DIMN 16
#define TPT  4            // float2 tasks per thread per tile
#define NCTA 444          // 3 per SM x 148, persistent

typedef unsigned long long ull;

__device__ __forceinline__ ull dup2f(float v) {
    ull r;
    asm("mov.b64 %0, {%1, %1};" : "=l"(r) : "f"(v));
    return r;
}
__device__ __forceinline__ void unpack2f(ull v, float& lo, float& hi) {
    asm("mov.b64 {%0, %1}, %2;" : "=f"(lo), "=f"(hi) : "l"(v));
}
__device__ __forceinline__ void ffma2(ull& d, ull a, ull b) {
    asm("fma.rn.f32x2 %0, %1, %2, %3;" : "=l"(d) : "l"(a), "l"(b), "l"(d));
}
__device__ __forceinline__ ull mul2(ull a, ull b) {
    ull r;
    asm("mul.rn.f32x2 %0, %1, %2;" : "=l"(r) : "l"(a), "l"(b));
    return r;
}
__device__ __forceinline__ ull add2(ull a, ull b) {
    ull r;
    asm("add.rn.f32x2 %0, %1, %2;" : "=l"(r) : "l"(a), "l"(b));
    return r;
}

__device__ __forceinline__ void load_tile(float2 v[TPT],
                                          const float2* __restrict__ gin,
                                          int base, int total2) {
#pragma unroll
    for (int k = 0; k < TPT; k++) {
        int p = base + k * 256;
        v[k] = (p < total2) ? __ldcs(&gin[p]) : make_float2(0.f, 0.f);
    }
}

__device__ __forceinline__ void compute_store(const float2 v[TPT],
                                              float2* __restrict__ gout,
                                              int base, int total2, int dlt,
                                              const ull Mreg[4][4], ull cb) {
#pragma unroll
    for (int k = 0; k < TPT; k++) {
        // Share inputs within the lane pair (o, o^1).
        float px = __shfl_xor_sync(0xffffffffu, v[k].x, 1);
        float py = __shfl_xor_sync(0xffffffffu, v[k].y, 1);
        ull xd0 = dup2f(v[k].x);
        ull xd1 = dup2f(v[k].y);
        ull xd2 = dup2f(px);
        ull xd3 = dup2f(py);

        // Partials for my 4 output pairs (half H), depth-4 chains.
        ull P[4];
#pragma unroll
        for (int m = 0; m < 4; m++) {
            P[m] = mul2(Mreg[0][m], xd0);
            ffma2(P[m], Mreg[1][m], xd1);
            ffma2(P[m], Mreg[2][m], xd2);
            ffma2(P[m], Mreg[3][m], xd3);
        }

        // Reduce-scatter over input quarters: xor2 then xor4 on lanes.
        ull A0 = add2(P[0], __shfl_xor_sync(0xffffffffu, P[1], 2));
        ull A1 = add2(P[2], __shfl_xor_sync(0xffffffffu, P[3], 2));
        ull F  = add2(A0, __shfl_xor_sync(0xffffffffu, A1, 4));
        F = add2(F, cb);

        int p = base + k * 256;
        if (p < total2) {                      // total2 % 8 == 0 -> row-safe
            float lo, hi;
            unpack2f(F, lo, hi);
            __stcs(&gout[p + dlt], make_float2(lo, hi));
        }
    }
}

__global__ __launch_bounds__(256, 3)
void xattn_kernel(const float2* __restrict__ gin,
                  float2* __restrict__ gout,
                  const float* __restrict__ w_in,
                  const float* __restrict__ b_in,
                  const float* __restrict__ w_out,
                  const float* __restrict__ b_out,
                  int total2, int ntiles) {
    __shared__ __align__(16) float2 sB[128];  // [i*8 + p] = (M[2p][i], M[2p+1][i])
    __shared__ float2 sC[8];                  // [p] = (c[2p], c[2p+1])

    int t = threadIdx.x;

    // ---- per-CTA weight folding (replaces separate setup kernel) ----
    if (t < 128) {
        int i = t >> 3, p = t & 7;
        float m0 = 0.f, m1 = 0.f;
#pragma unroll
        for (int k = 0; k < DIMN; k++) {
            float wv = w_in[(2 * DIMN + k) * DIMN + i];   // Wv rows 32..47, col i
            m0 += w_out[(2 * p) * DIMN + k] * wv;
            m1 += w_out[(2 * p + 1) * DIMN + k] * wv;
        }
        sB[t] = make_float2(m0, m1);
        if (i == 0) {
            float c0 = b_out[2 * p], c1 = b_out[2 * p + 1];
#pragma unroll
            for (int k = 0; k < DIMN; k++) {
                float bv = b_in[2 * DIMN + k];
                c0 += w_out[(2 * p) * DIMN + k] * bv;
                c1 += w_out[(2 * p + 1) * DIMN + k] * bv;
            }
            sC[p] = make_float2(c0, c1);
        }
    }
    __syncthreads();

    const int o = t & 7;          // float2 slot within row
    const int H = o & 1;          // my output half
    const int g = o >> 1 & 3;     // my (shared) input quarter
    const int dlt = 4 * H + g - o;  // store-slot delta within the row

    // M columns for inputs 4g..4g+3 (mine first, partner's after),
    // for output pairs pr(m) = 4H + (g^m).
    const int i0 = 4 * g + 2 * H;        // my two inputs
    const int i2 = 4 * g + 2 * (H ^ 1);  // partner's two inputs
    ull Mreg[4][4];
#pragma unroll
    for (int m = 0; m < 4; m++) {
        int pr = 4 * H + (g ^ m);
        Mreg[0][m] = *(const ull*)&sB[(i0    ) * 8 + pr];
        Mreg[1][m] = *(const ull*)&sB[(i0 + 1) * 8 + pr];
        Mreg[2][m] = *(const ull*)&sB[(i2    ) * 8 + pr];
        Mreg[3][m] = *(const ull*)&sB[(i2 + 1) * 8 + pr];
    }
    ull cb = *(const ull*)&sC[4 * H + g];

    const int stride = gridDim.x;
    int tile = blockIdx.x;
    if (tile >= ntiles) return;

    const int TB = 256 * TPT;     // float2s per tile
    float2 va[TPT], vb[TPT];

    load_tile(va, gin, tile * TB + t, total2);

    while (true) {
        int n1 = tile + stride;
        if (n1 < ntiles) load_tile(vb, gin, n1 * TB + t, total2);
        compute_store(va, gout, tile * TB + t, total2, dlt, Mreg, cb);
        if (n1 >= ntiles) return;

        int n2 = n1 + stride;
        if (n2 < ntiles) load_tile(va, gin, n2 * TB + t, total2);
        compute_store(vb, gout, n1 * TB + t, total2, dlt, Mreg, cb);
        if (n2 >= ntiles) return;

        tile = n2;
    }
}

extern "C" void kernel_launch(void* const* d_in, const int* in_sizes, int n_in,
                              void* d_out, int out_size) {
    // inputs: 0 fp_16 (unused), 1 chem_16, 2 in_proj_weight, 3 in_proj_bias,
    //         4 out_proj_weight, 5 out_proj_bias
    const float* chem  = (const float*)d_in[1];
    const float* w_in  = (const float*)d_in[2];
    const float* b_in  = (const float*)d_in[3];
    const float* w_out = (const float*)d_in[4];
    const float* b_out = (const float*)d_in[5];

    int total2 = in_sizes[1] / 2;            // float2 count (multiple of 8)
    int tb = 256 * TPT;
    int ntiles = (total2 + tb - 1) / tb;
    int blocks = ntiles < NCTA ? ntiles : NCTA;

    xattn_kernel<<<blocks, 256>>>((const float2*)chem, (float2*)d_out,
                                  w_in, b_in, w_out, b_out, total2, ntiles);
}

// round 9
// speedup vs baseline: 1.0720x; 1.0720x over previous
#include <cuda_runtime.h>

// out = chem @ (Wout @ Wv)^T + (Wout @ bv + bout)   (softmax over singleton == 1)
//
// Quad scheme (R7): lane owns float4 quarter q = t&3; partials for all 16
// outputs from its 4 values (M = 32 f32x2 regs, lane-permuted for const-index
// shfl), 2-round butterfly reduce-scatter -> lane stores its own quarter.
// NEW: persistent grid with a FOUR-buffer register pipeline (3 tiles in
// flight while one computes -> 48 KB/SM outstanding), TPT=2, int indexing,
// weight folding fused into the kernel (no setup launch).

#define DIMN 16
#define TPT  2            // float4 tasks per thread per tile
#define NCTA 296          // 2 per SM, persistent

typedef unsigned long long ull;

__device__ __forceinline__ ull dup2f(float v) {
    ull r;
    asm("mov.b64 %0, {%1, %1};" : "=l"(r) : "f"(v));
    return r;
}
__device__ __forceinline__ void unpack2f(ull v, float& lo, float& hi) {
    asm("mov.b64 {%0, %1}, %2;" : "=f"(lo), "=f"(hi) : "l"(v));
}
__device__ __forceinline__ void ffma2(ull& d, ull a, ull b) {
    asm("fma.rn.f32x2 %0, %1, %2, %3;" : "=l"(d) : "l"(a), "l"(b), "l"(d));
}
__device__ __forceinline__ ull mul2(ull a, ull b) {
    ull r;
    asm("mul.rn.f32x2 %0, %1, %2;" : "=l"(r) : "l"(a), "l"(b));
    return r;
}
__device__ __forceinline__ ull add2(ull a, ull b) {
    ull r;
    asm("add.rn.f32x2 %0, %1, %2;" : "=l"(r) : "l"(a), "l"(b));
    return r;
}

#define TB (256 * TPT)    // float4s per tile

__device__ __forceinline__ void load_tile(float4 v[TPT],
                                          const float4* __restrict__ gin,
                                          int tile, int ntiles, int t,
                                          int total4) {
    if (tile >= ntiles) return;          // uniform guard
    int base = tile * TB + t;
#pragma unroll
    for (int k = 0; k < TPT; k++) {
        int p = base + k * 256;
        v[k] = (p < total4) ? __ldcs(&gin[p]) : make_float4(0.f, 0.f, 0.f, 0.f);
    }
}

__device__ __forceinline__ void compute_store(const float4 v[TPT],
                                              float4* __restrict__ gout,
                                              int tile, int t, int total4,
                                              const ull Mreg[4][8],
                                              ull cA, ull cB) {
    int base = tile * TB + t;
#pragma unroll
    for (int k = 0; k < TPT; k++) {
        // Partials for all 16 outputs from my 4 values (depth-4 chains).
        ull P[8];
        ull xd = dup2f(v[k].x);
#pragma unroll
        for (int m = 0; m < 8; m++) P[m] = mul2(Mreg[0][m], xd);
        xd = dup2f(v[k].y);
#pragma unroll
        for (int m = 0; m < 8; m++) ffma2(P[m], Mreg[1][m], xd);
        xd = dup2f(v[k].z);
#pragma unroll
        for (int m = 0; m < 8; m++) ffma2(P[m], Mreg[2][m], xd);
        xd = dup2f(v[k].w);
#pragma unroll
        for (int m = 0; m < 8; m++) ffma2(P[m], Mreg[3][m], xd);

        // Butterfly reduce-scatter across the lane-quad (const offsets).
        ull A0 = add2(P[0], __shfl_xor_sync(0xffffffffu, P[4], 2));
        ull A1 = add2(P[1], __shfl_xor_sync(0xffffffffu, P[5], 2));
        ull A2 = add2(P[2], __shfl_xor_sync(0xffffffffu, P[6], 2));
        ull A3 = add2(P[3], __shfl_xor_sync(0xffffffffu, P[7], 2));
        ull F0 = add2(A0, __shfl_xor_sync(0xffffffffu, A2, 1));
        ull F1 = add2(A1, __shfl_xor_sync(0xffffffffu, A3, 1));
        F0 = add2(F0, cA);
        F1 = add2(F1, cB);

        int p = base + k * 256;
        if (p < total4) {
            float o0, o1, o2, o3;
            unpack2f(F0, o0, o1);
            unpack2f(F1, o2, o3);
            __stcs(&gout[p], make_float4(o0, o1, o2, o3));
        }
    }
}

__global__ __launch_bounds__(256, 2)
void xattn_kernel(const float4* __restrict__ gin,
                  float4* __restrict__ gout,
                  const float* __restrict__ w_in,
                  const float* __restrict__ b_in,
                  const float* __restrict__ w_out,
                  const float* __restrict__ b_out,
                  int total4, int ntiles) {
    __shared__ __align__(16) float2 sB[128];  // [i*8 + p] = (M[2p][i], M[2p+1][i])
    __shared__ float2 sC[8];                  // [p] = (c[2p], c[2p+1])

    int t = threadIdx.x;

    // ---- per-CTA weight folding (no separate setup launch) ----
    if (t < 128) {
        int i = t >> 3, p = t & 7;
        float m0 = 0.f, m1 = 0.f;
#pragma unroll
        for (int k = 0; k < DIMN; k++) {
            float wv = w_in[(2 * DIMN + k) * DIMN + i];   // Wv rows 32..47, col i
            m0 += w_out[(2 * p) * DIMN + k] * wv;
            m1 += w_out[(2 * p + 1) * DIMN + k] * wv;
        }
        sB[t] = make_float2(m0, m1);
        if (i == 0) {
            float c0 = b_out[2 * p], c1 = b_out[2 * p + 1];
#pragma unroll
            for (int k = 0; k < DIMN; k++) {
                float bv = b_in[2 * DIMN + k];
                c0 += w_out[(2 * p) * DIMN + k] * bv;
                c1 += w_out[(2 * p + 1) * DIMN + k] * bv;
            }
            sC[p] = make_float2(c0, c1);
        }
    }
    __syncthreads();

    const int q = t & 3;                 // my input AND output quarter

    // M columns for my quarter, lane-permuted for compile-time shfl indices.
    // Mreg[il][2u+v] = (M[4*(q^u)+2v][4q+il], M[4*(q^u)+2v+1][4q+il])
    ull Mreg[4][8];
#pragma unroll
    for (int il = 0; il < 4; il++) {
        int i = 4 * q + il;
#pragma unroll
        for (int u = 0; u < 4; u++) {
#pragma unroll
            for (int v = 0; v < 2; v++)
                Mreg[il][2 * u + v] = *(const ull*)&sB[i * 8 + 2 * (q ^ u) + v];
        }
    }
    ull cA = *(const ull*)&sC[2 * q + 0];
    ull cB = *(const ull*)&sC[2 * q + 1];

    const int S = gridDim.x;
    int T = blockIdx.x;
    if (T >= ntiles) return;

    float4 v0[TPT], v1[TPT], v2[TPT], v3[TPT];

    // Prologue: 3 tiles in flight before first compute.
    load_tile(v0, gin, T,         ntiles, t, total4);
    load_tile(v1, gin, T + S,     ntiles, t, total4);
    load_tile(v2, gin, T + 2 * S, ntiles, t, total4);

    while (true) {
        load_tile(v3, gin, T + 3 * S, ntiles, t, total4);
        compute_store(v0, gout, T, t, total4, Mreg, cA, cB);
        T += S; if (T >= ntiles) return;

        load_tile(v0, gin, T + 3 * S, ntiles, t, total4);
        compute_store(v1, gout, T, t, total4, Mreg, cA, cB);
        T += S; if (T >= ntiles) return;

        load_tile(v1, gin, T + 3 * S, ntiles, t, total4);
        compute_store(v2, gout, T, t, total4, Mreg, cA, cB);
        T += S; if (T >= ntiles) return;

        load_tile(v2, gin, T + 3 * S, ntiles, t, total4);
        compute_store(v3, gout, T, t, total4, Mreg, cA, cB);
        T += S; if (T >= ntiles) return;
    }
}

extern "C" void kernel_launch(void* const* d_in, const int* in_sizes, int n_in,
                              void* d_out, int out_size) {
    // inputs: 0 fp_16 (unused), 1 chem_16, 2 in_proj_weight, 3 in_proj_bias,
    //         4 out_proj_weight, 5 out_proj_bias
    const float* chem  = (const float*)d_in[1];
    const float* w_in  = (const float*)d_in[2];
    const float* b_in  = (const float*)d_in[3];
    const float* w_out = (const float*)d_in[4];
    const float* b_out = (const float*)d_in[5];

    int total4 = in_sizes[1] / 4;            // float4 count
    int ntiles = (total4 + TB - 1) / TB;
    int blocks = ntiles < NCTA ? ntiles : NCTA;

    xattn_kernel<<<blocks, 256>>>((const float4*)chem, (float4*)d_out,
                                  w_in, b_in, w_out, b_out, total4, ntiles);
}